// round 10
// baseline (speedup 1.0000x reference)
#include <cuda_runtime.h>
#include <cuda_fp16.h>
#include <cuda_bf16.h>
#include <cstddef>
#include <cstdint>

// ---------------------------------------------------------------------------
// GCN: 5 GraphConv + 3 edge-weighted aggregations. CSR-gather + tensor cores.
// R10 = R5/R9 baseline (321.4us) with ONE hot-path change: gather_h_k widened
// from 8 to 16 halves per thread (2 independent uint4 loads per edge, x2 edge
// unroll -> 4 loads in flight) for more memory-level parallelism.
// Preprocessing frozen at R5 form (R6-R8 consolidation cost ~70us — confirmed).
// ---------------------------------------------------------------------------

#define NN 50000
#define NE 800000

__device__ int   g_ideg[NN];
__device__ int   g_odeg[NN];
__device__ int   g_cnt[NN];
__device__ int   g_off[NN + 1];
__device__ __align__(16) int2  g_edge[NE];   // {src, __float_as_int(efet)}
__device__ float g_norm_out[NN];
__device__ float g_norm_in[NN];
__device__ __align__(16) float g_bufA[(size_t)NN * 256];
__device__ __align__(16) float g_bufB[(size_t)NN * 256];
__device__ __align__(16) float g_bufC[(size_t)NN * 256];
// transposed fp16 weights: W2t[128][256], W3t[64][128], W4t[32][64]
__device__ __align__(16) __half g_w2t[128 * 256];
__device__ __align__(16) __half g_w3t[64 * 128];
__device__ __align__(16) __half g_w4t[32 * 64];

// ---- degrees / norms -------------------------------------------------------

__global__ void deg_k(const int* __restrict__ src, const int* __restrict__ dst) {
    int e = blockIdx.x * blockDim.x + threadIdx.x;
    if (e < NE) {
        atomicAdd(&g_odeg[src[e]], 1);
        atomicAdd(&g_ideg[dst[e]], 1);
    }
}

__global__ void norm_k() {
    int i = blockIdx.x * blockDim.x + threadIdx.x;
    if (i < NN) {
        g_norm_out[i] = rsqrtf(fmaxf((float)g_odeg[i], 1.0f));
        g_norm_in[i]  = rsqrtf(fmaxf((float)g_ideg[i], 1.0f));
    }
}

// ---- exclusive scan of in-degrees -> CSR offsets (single block) ------------

__global__ void scan_k() {
    __shared__ int sh[1024];
    const int t = threadIdx.x;
    const int CH = (NN + 1023) / 1024;
    int beg = t * CH, end = min(beg + CH, NN);
    int s = 0;
    for (int i = beg; i < end; i++) s += g_ideg[i];
    sh[t] = s;
    __syncthreads();
    for (int ofs = 1; ofs < 1024; ofs <<= 1) {
        int v = (t >= ofs) ? sh[t - ofs] : 0;
        __syncthreads();
        sh[t] += v;
        __syncthreads();
    }
    int run = (t == 0) ? 0 : sh[t - 1];
    for (int i = beg; i < end; i++) { g_off[i] = run; run += g_ideg[i]; }
    if (end == NN) g_off[NN] = run;
}

__global__ void fill_k(const int* __restrict__ src, const int* __restrict__ dst,
                       const float* __restrict__ efet) {
    int e = blockIdx.x * blockDim.x + threadIdx.x;
    if (e < NE) {
        int d = dst[e];
        int pos = g_off[d] + atomicAdd(&g_cnt[d], 1);
        g_edge[pos] = make_int2(src[e], __float_as_int(efet[e]));
    }
}

// ---- W -> Wt fp16 transpose (tiny) -----------------------------------------

template <int K, int N>
__global__ void wcvt_k(const float* __restrict__ W, __half* __restrict__ Wt) {
    int i = blockIdx.x * blockDim.x + threadIdx.x;
    if (i < K * N) {
        int k = i / N, n = i % N;
        Wt[(size_t)n * K + k] = __float2half(W[i]);
    }
}

// ---- fp32 gather (16 pre-agg, 4 final) -------------------------------------
// WMODE: 0 = w=1, 1 = w=efet, 2 = w=out_norm[src]

template <int F, int WMODE, bool EPI, bool RELU>
__global__ void gather_k(const float* __restrict__ m,
                         const float* __restrict__ b,
                         float* __restrict__ out) {
    constexpr int NT = F / 4;
    constexpr int NPB = 256 / NT;
    int t = threadIdx.x;
    int node = blockIdx.x * NPB + t / NT;
    int c = t % NT;
    if (node >= NN) return;
    int beg = g_off[node], end = g_off[node + 1];

    float4 acc = make_float4(0.f, 0.f, 0.f, 0.f);
    for (int e = beg; e < end; e++) {
        int2 sc = g_edge[e];
        int s = sc.x;
        float w = 1.0f;
        if (WMODE == 1) w = __int_as_float(sc.y);
        if (WMODE == 2) w = g_norm_out[s];
        float4 v = *(const float4*)(m + (size_t)s * F + c * 4);
        acc.x += v.x * w; acc.y += v.y * w; acc.z += v.z * w; acc.w += v.w * w;
    }
    if (EPI) {
        float ni = g_norm_in[node];
        acc.x = acc.x * ni + b[c * 4 + 0];
        acc.y = acc.y * ni + b[c * 4 + 1];
        acc.z = acc.z * ni + b[c * 4 + 2];
        acc.w = acc.w * ni + b[c * 4 + 3];
    }
    if (RELU) {
        acc.x = fmaxf(acc.x, 0.f); acc.y = fmaxf(acc.y, 0.f);
        acc.z = fmaxf(acc.z, 0.f); acc.w = fmaxf(acc.w, 0.f);
    }
    *(float4*)(out + (size_t)node * F + c * 4) = acc;
}

// ---- fp16-input gather ------------------------------------------------------
// R10: 16 halves (two uint4) per thread, fp32 accumulation, x2 edge unroll
// -> 4 independent 16B loads in flight per thread.
// ONORM: multiply final (post-relu) result by out_norm[node] (feeds mma GEMM).
// OH: fp16 output.

__device__ __forceinline__ void acc8(float* a, uint4 r, float w) {
    float2 f;
    f = __half22float2(*(const __half2*)&r.x); a[0] += f.x * w; a[1] += f.y * w;
    f = __half22float2(*(const __half2*)&r.y); a[2] += f.x * w; a[3] += f.y * w;
    f = __half22float2(*(const __half2*)&r.z); a[4] += f.x * w; a[5] += f.y * w;
    f = __half22float2(*(const __half2*)&r.w); a[6] += f.x * w; a[7] += f.y * w;
}

template <int F, int WMODE, bool EPI, bool RELU, bool ONORM, bool OH>
__global__ void gather_h_k(const __half* __restrict__ m,
                           const float* __restrict__ b,
                           void* __restrict__ outp) {
    constexpr int RS = F / 8;          // row stride in uint4s
    constexpr int NT = F / 16;         // threads per node (16 halves each)
    constexpr int NPB = 256 / NT;
    int t = threadIdx.x;
    int node = blockIdx.x * NPB + t / NT;
    int c = t % NT;                    // 16-half chunk index
    if (node >= NN) return;
    int beg = g_off[node], end = g_off[node + 1];

    float acc[16];
#pragma unroll
    for (int i = 0; i < 16; i++) acc[i] = 0.f;

    const uint4* base = (const uint4*)m;
    int e = beg;
    for (; e + 2 <= end; e += 2) {
        int2 sc0 = g_edge[e], sc1 = g_edge[e + 1];
        float w0 = 1.f, w1 = 1.f;
        if (WMODE == 1) { w0 = __int_as_float(sc0.y); w1 = __int_as_float(sc1.y); }
        const uint4* p0 = base + (size_t)sc0.x * RS + c * 2;
        const uint4* p1 = base + (size_t)sc1.x * RS + c * 2;
        uint4 r0a = p0[0], r0b = p0[1];
        uint4 r1a = p1[0], r1b = p1[1];
        acc8(acc,     r0a, w0);
        acc8(acc + 8, r0b, w0);
        acc8(acc,     r1a, w1);
        acc8(acc + 8, r1b, w1);
    }
    if (e < end) {
        int2 sc = g_edge[e];
        float w = (WMODE == 1) ? __int_as_float(sc.y) : 1.f;
        const uint4* p = base + (size_t)sc.x * RS + c * 2;
        uint4 ra = p[0], rb = p[1];
        acc8(acc,     ra, w);
        acc8(acc + 8, rb, w);
    }

    if (EPI) {
        float ni = g_norm_in[node];
#pragma unroll
        for (int i = 0; i < 16; i++) acc[i] = acc[i] * ni + b[c * 16 + i];
    }
    if (RELU) {
#pragma unroll
        for (int i = 0; i < 16; i++) acc[i] = fmaxf(acc[i], 0.f);
    }
    if (ONORM) {
        float no = g_norm_out[node];
#pragma unroll
        for (int i = 0; i < 16; i++) acc[i] *= no;
    }
    if (OH) {
        uint4 r[2];
#pragma unroll
        for (int h = 0; h < 2; h++) {
            __half2 h0 = __floats2half2_rn(acc[h * 8 + 0], acc[h * 8 + 1]);
            __half2 h1 = __floats2half2_rn(acc[h * 8 + 2], acc[h * 8 + 3]);
            __half2 h2 = __floats2half2_rn(acc[h * 8 + 4], acc[h * 8 + 5]);
            __half2 h3 = __floats2half2_rn(acc[h * 8 + 6], acc[h * 8 + 7]);
            r[h].x = *(const unsigned*)&h0; r[h].y = *(const unsigned*)&h1;
            r[h].z = *(const unsigned*)&h2; r[h].w = *(const unsigned*)&h3;
        }
        uint4* o = (uint4*)outp + (size_t)node * RS + c * 2;
        o[0] = r[0];
        o[1] = r[1];
    } else {
        float* o = (float*)outp + (size_t)node * F + c * 16;
#pragma unroll
        for (int h = 0; h < 4; h++)
            *(float4*)(o + h * 4) = make_float4(acc[h * 4 + 0], acc[h * 4 + 1],
                                                acc[h * 4 + 2], acc[h * 4 + 3]);
    }
}

// ---- tensor-core GEMM: D[M,N] = A[M,K] @ W[K,N], fp16 in / fp32 acc --------
// A row-major fp16 (out_norm pre-folded). Wt[N,K] row-major fp16 (transposed).

template <int K, int N>
__global__ void mma_gemm_k(const __half* __restrict__ A,
                           const __half* __restrict__ Wt,
                           __half* __restrict__ D) {
    constexpr int WN = (N >= 64) ? 64 : N;       // warp n-extent
    constexpr int TN = WN / 8;                   // n8 tiles per warp
    constexpr int WARPS_N = N / WN;
    constexpr int WARPS_M = 8 / WARPS_N;
    constexpr int BM = WARPS_M * 16;
    constexpr int PITCH = K + 8;                 // +16B pad -> bank rotation
    constexpr int KC = K / 16;                   // k16 chunks

    __shared__ __half sA[BM * PITCH];

    const int tid = threadIdx.x;
    const int lane = tid & 31;
    const int wid = tid >> 5;
    const int wm = wid % WARPS_M;
    const int wn = wid / WARPS_M;
    const int blockStart = blockIdx.x * BM;

    for (int i = tid; i < BM * (K / 8); i += 256) {
        int row = i / (K / 8), chunk = i % (K / 8);
        int node = blockStart + row;
        uint4 v = make_uint4(0, 0, 0, 0);
        if (node < NN) v = ((const uint4*)A)[(size_t)node * (K / 8) + chunk];
        *(uint4*)(&sA[row * PITCH + chunk * 8]) = v;
    }
    __syncthreads();

    float acc[TN][4];
#pragma unroll
    for (int t = 0; t < TN; t++)
#pragma unroll
        for (int i = 0; i < 4; i++) acc[t][i] = 0.f;

    const int q = lane >> 3, r = lane & 7;
    const int arow = wm * 16 + r + 8 * (q & 1);
    const int acol0 = 8 * (q >> 1);
    unsigned abase;
    {
        const void* p = &sA[arow * PITCH + acol0];
        asm("{ .reg .u64 t; cvta.to.shared.u64 t, %1; cvt.u32.u64 %0, t; }"
            : "=r"(abase) : "l"(p));
    }

    const __half* wbase = Wt + (size_t)(wn * WN + (lane >> 2)) * K + (lane & 3) * 2;

#pragma unroll
    for (int kc = 0; kc < KC; kc++) {
        unsigned a0, a1, a2, a3;
        asm volatile("ldmatrix.sync.aligned.m8n8.x4.shared.b16 {%0,%1,%2,%3}, [%4];"
                     : "=r"(a0), "=r"(a1), "=r"(a2), "=r"(a3)
                     : "r"(abase + kc * 32));
#pragma unroll
        for (int tn = 0; tn < TN; tn++) {
            unsigned b0 = *(const unsigned*)(wbase + (size_t)tn * 8 * K + kc * 16);
            unsigned b1 = *(const unsigned*)(wbase + (size_t)tn * 8 * K + kc * 16 + 8);
            asm volatile(
                "mma.sync.aligned.m16n8k16.row.col.f32.f16.f16.f32 "
                "{%0,%1,%2,%3}, {%4,%5,%6,%7}, {%8,%9}, {%0,%1,%2,%3};"
                : "+f"(acc[tn][0]), "+f"(acc[tn][1]), "+f"(acc[tn][2]), "+f"(acc[tn][3])
                : "r"(a0), "r"(a1), "r"(a2), "r"(a3), "r"(b0), "r"(b1));
        }
    }

    const int node0 = blockStart + wm * 16 + (lane >> 2);
    const int node1 = node0 + 8;
#pragma unroll
    for (int tn = 0; tn < TN; tn++) {
        int gcol = wn * WN + tn * 8 + (lane & 3) * 2;
        if (node0 < NN) {
            __half2 h = __floats2half2_rn(acc[tn][0], acc[tn][1]);
            *(unsigned*)(D + (size_t)node0 * N + gcol) = *(const unsigned*)&h;
        }
        if (node1 < NN) {
            __half2 h = __floats2half2_rn(acc[tn][2], acc[tn][3]);
            *(unsigned*)(D + (size_t)node1 * N + gcol) = *(const unsigned*)&h;
        }
    }
}

// ---- gemm1: agg16 @ W1 (16x256), fused in_norm+bias+relu, fp16 out ---------

__global__ void gemm1_k(const float* __restrict__ h, const float* __restrict__ W,
                        const float* __restrict__ b, __half* __restrict__ out) {
    __shared__ float sh[64 * 16];
    const int j = threadIdx.x;
    float w[16];
#pragma unroll
    for (int k = 0; k < 16; k++) w[k] = W[k * 256 + j];
    float bj = b[j];
    int nbase = blockIdx.x * 64;
    for (int i = j; i < 64 * 16; i += 256) {
        int node = nbase + i / 16;
        sh[i] = (node < NN) ? h[(size_t)node * 16 + (i % 16)] : 0.f;
    }
    __syncthreads();
#pragma unroll 4
    for (int ln = 0; ln < 64; ln++) {
        int node = nbase + ln;
        if (node >= NN) break;
        float acc = 0.f;
#pragma unroll
        for (int k = 0; k < 16; k++) acc += sh[ln * 16 + k] * w[k];
        acc = acc * g_norm_in[node] + bj;
        out[(size_t)node * 256 + j] = __float2half(fmaxf(acc, 0.f));
    }
}

// ---- gemm5: 32 -> 4 (tiny fp32), thread = node -----------------------------

__global__ void gemm5_k(const float* __restrict__ h, const float* __restrict__ W,
                        float* __restrict__ out) {
    __shared__ float sw[32 * 4];
    if (threadIdx.x < 128) sw[threadIdx.x] = W[threadIdx.x];
    __syncthreads();
    int node = blockIdx.x * 256 + threadIdx.x;
    if (node >= NN) return;
    float no = g_norm_out[node];
    float acc[4] = {0.f, 0.f, 0.f, 0.f};
    const float4* row = (const float4*)(h + (size_t)node * 32);
#pragma unroll
    for (int k4 = 0; k4 < 8; k4++) {
        float4 v = row[k4];
        float vv[4] = {v.x * no, v.y * no, v.z * no, v.w * no};
#pragma unroll
        for (int i = 0; i < 4; i++)
#pragma unroll
            for (int j = 0; j < 4; j++)
                acc[j] += vv[i] * sw[(k4 * 4 + i) * 4 + j];
    }
    *(float4*)(out + (size_t)node * 4) = make_float4(acc[0], acc[1], acc[2], acc[3]);
}

// ---------------------------------------------------------------------------

static inline int cdiv(long long a, int b) { return (int)((a + b - 1) / b); }

extern "C" void kernel_launch(void* const* d_in, const int* in_sizes, int n_in,
                              void* d_out, int out_size) {
    (void)in_sizes; (void)n_in; (void)out_size;
    const float* x    = (const float*)d_in[0];
    const float* efet = (const float*)d_in[1];
    const int*   src  = (const int*)d_in[2];
    const int*   dst  = (const int*)d_in[3];
    const float* W1 = (const float*)d_in[4];  const float* b1 = (const float*)d_in[5];
    const float* W2 = (const float*)d_in[6];  const float* b2 = (const float*)d_in[7];
    const float* W3 = (const float*)d_in[8];  const float* b3 = (const float*)d_in[9];
    const float* W4 = (const float*)d_in[10]; const float* b4 = (const float*)d_in[11];
    const float* W5 = (const float*)d_in[12]; const float* b5 = (const float*)d_in[13];
    float* out = (float*)d_out;

    float *bufA, *bufB, *bufC;
    int *ideg, *odeg, *cnt;
    __half *w2t, *w3t, *w4t;
    cudaGetSymbolAddress((void**)&bufA, g_bufA);
    cudaGetSymbolAddress((void**)&bufB, g_bufB);
    cudaGetSymbolAddress((void**)&bufC, g_bufC);
    cudaGetSymbolAddress((void**)&ideg, g_ideg);
    cudaGetSymbolAddress((void**)&odeg, g_odeg);
    cudaGetSymbolAddress((void**)&cnt,  g_cnt);
    cudaGetSymbolAddress((void**)&w2t, g_w2t);
    cudaGetSymbolAddress((void**)&w3t, g_w3t);
    cudaGetSymbolAddress((void**)&w4t, g_w4t);
    __half* hA = (__half*)bufA;
    __half* hB = (__half*)bufB;
    __half* hC = (__half*)bufC;

    const int TB = 256;

    // ---- preprocessing: degrees, norms, CSR, fp16 transposed weights (R5 form)
    cudaMemsetAsync(ideg, 0, NN * sizeof(int));
    cudaMemsetAsync(odeg, 0, NN * sizeof(int));
    cudaMemsetAsync(cnt,  0, NN * sizeof(int));
    deg_k<<<cdiv(NE, TB), TB>>>(src, dst);
    norm_k<<<cdiv(NN, TB), TB>>>();
    scan_k<<<1, 1024>>>();
    fill_k<<<cdiv(NE, TB), TB>>>(src, dst, efet);
    wcvt_k<256, 128><<<cdiv(256 * 128, TB), TB>>>(W2, w2t);
    wcvt_k<128, 64><<<cdiv(128 * 64, TB), TB>>>(W3, w3t);
    wcvt_k<64, 32><<<cdiv(64 * 32, TB), TB>>>(W4, w4t);

    // ---- gc1: pre-aggregate 16-wide scaled x, matmul+epi+relu -> h1 fp16
    gather_k<16, 2, false, false><<<cdiv(NN, 64), TB>>>(x, nullptr, bufA);
    gemm1_k<<<cdiv(NN, 64), TB>>>(bufA, W1, b1, hB);                         // h1: hB

    // ---- ewa1 (256) + relu, *out_norm -> fp16 A-operand
    gather_h_k<256, 1, false, true, true, true><<<cdiv(NN, 16), TB>>>(hB, nullptr, hA);

    // ---- gc2: mma 256->128; agg + epi + relu -> h2 fp16
    mma_gemm_k<256, 128><<<cdiv(NN, 64), TB>>>(hA, w2t, hB);                 // m2: hB
    gather_h_k<128, 0, true, true, false, true><<<cdiv(NN, 32), TB>>>(hB, b2, hC); // h2: hC

    // ---- ewa2 (128) + relu, *out_norm -> fp16
    gather_h_k<128, 1, false, true, true, true><<<cdiv(NN, 32), TB>>>(hC, nullptr, hA);

    // ---- gc3: mma 128->64; agg + epi + relu -> h3 fp16
    mma_gemm_k<128, 64><<<cdiv(NN, 128), TB>>>(hA, w3t, hB);                 // m3: hB
    gather_h_k<64, 0, true, true, false, true><<<cdiv(NN, 64), TB>>>(hB, b3, hC);  // h3: hC

    // ---- ewa3 (64) + relu, *out_norm -> fp16
    gather_h_k<64, 1, false, true, true, true><<<cdiv(NN, 64), TB>>>(hC, nullptr, hA);

    // ---- gc4: mma 64->32; agg + epi + relu -> h4 fp32
    mma_gemm_k<64, 32><<<cdiv(NN, 128), TB>>>(hA, w4t, hB);                  // m4: hB fp16
    gather_h_k<32, 0, true, true, false, false><<<cdiv(NN, 128), TB>>>(hB, b4, bufC); // h4: C fp32

    // ---- gc5: 32 -> 4 fp32 (epi, no relu)
    gemm5_k<<<cdiv(NN, 256), TB>>>(bufC, W5, bufB);
    gather_k<4, 0, true, false><<<cdiv(NN, 256), TB>>>(bufB, b5, out);
}

// round 11
// speedup vs baseline: 1.1586x; 1.1586x over previous
#include <cuda_runtime.h>
#include <cuda_fp16.h>
#include <cuda_bf16.h>
#include <cstddef>
#include <cstdint>

// ---------------------------------------------------------------------------
// GCN: 5 GraphConv + 3 edge-weighted aggregations. CSR-gather + tensor cores.
// R11 = R9 baseline (321.4us) + ewa/matmul commutation:
//   efet >= 0 and ewa inputs are post-relu (>= 0), so relu(ewa(g)) == ewa(g),
//   and (ewa(g)*no) @ W == no * ewa(g @ W).  Run each mma GEMM BEFORE its ewa
//   gather: ewa widths drop 256->128, 128->64, 64->32 (~360MB less L2 gather
//   traffic + proportional instruction work). Gather config frozen at R9 form
//   (8 halves/thread — R10 showed wider is slower).
// ---------------------------------------------------------------------------

#define NN 50000
#define NE 800000

__device__ int   g_ideg[NN];
__device__ int   g_odeg[NN];
__device__ int   g_cnt[NN];
__device__ int   g_off[NN + 1];
__device__ __align__(16) int2  g_edge[NE];   // {src, __float_as_int(efet)}
__device__ float g_norm_out[NN];
__device__ float g_norm_in[NN];
__device__ __align__(16) float g_bufA[(size_t)NN * 256];
__device__ __align__(16) float g_bufB[(size_t)NN * 256];
__device__ __align__(16) float g_bufC[(size_t)NN * 256];
// transposed fp16 weights: W2t[128][256], W3t[64][128], W4t[32][64]
__device__ __align__(16) __half g_w2t[128 * 256];
__device__ __align__(16) __half g_w3t[64 * 128];
__device__ __align__(16) __half g_w4t[32 * 64];

// ---- degrees / norms -------------------------------------------------------

__global__ void deg_k(const int* __restrict__ src, const int* __restrict__ dst) {
    int e = blockIdx.x * blockDim.x + threadIdx.x;
    if (e < NE) {
        atomicAdd(&g_odeg[src[e]], 1);
        atomicAdd(&g_ideg[dst[e]], 1);
    }
}

__global__ void norm_k() {
    int i = blockIdx.x * blockDim.x + threadIdx.x;
    if (i < NN) {
        g_norm_out[i] = rsqrtf(fmaxf((float)g_odeg[i], 1.0f));
        g_norm_in[i]  = rsqrtf(fmaxf((float)g_ideg[i], 1.0f));
    }
}

// ---- exclusive scan of in-degrees -> CSR offsets (single block) ------------

__global__ void scan_k() {
    __shared__ int sh[1024];
    const int t = threadIdx.x;
    const int CH = (NN + 1023) / 1024;
    int beg = t * CH, end = min(beg + CH, NN);
    int s = 0;
    for (int i = beg; i < end; i++) s += g_ideg[i];
    sh[t] = s;
    __syncthreads();
    for (int ofs = 1; ofs < 1024; ofs <<= 1) {
        int v = (t >= ofs) ? sh[t - ofs] : 0;
        __syncthreads();
        sh[t] += v;
        __syncthreads();
    }
    int run = (t == 0) ? 0 : sh[t - 1];
    for (int i = beg; i < end; i++) { g_off[i] = run; run += g_ideg[i]; }
    if (end == NN) g_off[NN] = run;
}

__global__ void fill_k(const int* __restrict__ src, const int* __restrict__ dst,
                       const float* __restrict__ efet) {
    int e = blockIdx.x * blockDim.x + threadIdx.x;
    if (e < NE) {
        int d = dst[e];
        int pos = g_off[d] + atomicAdd(&g_cnt[d], 1);
        g_edge[pos] = make_int2(src[e], __float_as_int(efet[e]));
    }
}

// ---- W -> Wt fp16 transpose (tiny) -----------------------------------------

template <int K, int N>
__global__ void wcvt_k(const float* __restrict__ W, __half* __restrict__ Wt) {
    int i = blockIdx.x * blockDim.x + threadIdx.x;
    if (i < K * N) {
        int k = i / N, n = i % N;
        Wt[(size_t)n * K + k] = __float2half(W[i]);
    }
}

// ---- fp32 gather (16 pre-agg, 4 final) -------------------------------------
// WMODE: 0 = w=1, 1 = w=efet, 2 = w=out_norm[src]

template <int F, int WMODE, bool EPI, bool RELU>
__global__ void gather_k(const float* __restrict__ m,
                         const float* __restrict__ b,
                         float* __restrict__ out) {
    constexpr int NT = F / 4;
    constexpr int NPB = 256 / NT;
    int t = threadIdx.x;
    int node = blockIdx.x * NPB + t / NT;
    int c = t % NT;
    if (node >= NN) return;
    int beg = g_off[node], end = g_off[node + 1];

    float4 acc = make_float4(0.f, 0.f, 0.f, 0.f);
    for (int e = beg; e < end; e++) {
        int2 sc = g_edge[e];
        int s = sc.x;
        float w = 1.0f;
        if (WMODE == 1) w = __int_as_float(sc.y);
        if (WMODE == 2) w = g_norm_out[s];
        float4 v = *(const float4*)(m + (size_t)s * F + c * 4);
        acc.x += v.x * w; acc.y += v.y * w; acc.z += v.z * w; acc.w += v.w * w;
    }
    if (EPI) {
        float ni = g_norm_in[node];
        acc.x = acc.x * ni + b[c * 4 + 0];
        acc.y = acc.y * ni + b[c * 4 + 1];
        acc.z = acc.z * ni + b[c * 4 + 2];
        acc.w = acc.w * ni + b[c * 4 + 3];
    }
    if (RELU) {
        acc.x = fmaxf(acc.x, 0.f); acc.y = fmaxf(acc.y, 0.f);
        acc.z = fmaxf(acc.z, 0.f); acc.w = fmaxf(acc.w, 0.f);
    }
    *(float4*)(out + (size_t)node * F + c * 4) = acc;
}

// ---- fp16-input gather ------------------------------------------------------
// 8 halves per thread, fp32 accumulation, x2 edge unroll (R9-frozen config).
// ONORM: multiply final result by out_norm[node].  OH: fp16 output.

__device__ __forceinline__ void acc8(float* a, uint4 r, float w) {
    float2 f;
    f = __half22float2(*(const __half2*)&r.x); a[0] += f.x * w; a[1] += f.y * w;
    f = __half22float2(*(const __half2*)&r.y); a[2] += f.x * w; a[3] += f.y * w;
    f = __half22float2(*(const __half2*)&r.z); a[4] += f.x * w; a[5] += f.y * w;
    f = __half22float2(*(const __half2*)&r.w); a[6] += f.x * w; a[7] += f.y * w;
}

template <int F, int WMODE, bool EPI, bool RELU, bool ONORM, bool OH>
__global__ void gather_h_k(const __half* __restrict__ m,
                           const float* __restrict__ b,
                           void* __restrict__ outp) {
    constexpr int NT = F / 8;
    constexpr int NPB = 256 / NT;
    int t = threadIdx.x;
    int node = blockIdx.x * NPB + t / NT;
    int c = t % NT;
    if (node >= NN) return;
    int beg = g_off[node], end = g_off[node + 1];

    float acc[8];
#pragma unroll
    for (int i = 0; i < 8; i++) acc[i] = 0.f;

    const uint4* base = (const uint4*)m;
    int e = beg;
    for (; e + 2 <= end; e += 2) {
        int2 sc0 = g_edge[e], sc1 = g_edge[e + 1];
        float w0 = 1.f, w1 = 1.f;
        if (WMODE == 1) { w0 = __int_as_float(sc0.y); w1 = __int_as_float(sc1.y); }
        uint4 r0 = base[(size_t)sc0.x * NT + c];
        uint4 r1 = base[(size_t)sc1.x * NT + c];
        acc8(acc, r0, w0);
        acc8(acc, r1, w1);
    }
    if (e < end) {
        int2 sc = g_edge[e];
        float w = (WMODE == 1) ? __int_as_float(sc.y) : 1.f;
        uint4 r = base[(size_t)sc.x * NT + c];
        acc8(acc, r, w);
    }

    if (EPI) {
        float ni = g_norm_in[node];
#pragma unroll
        for (int i = 0; i < 8; i++) acc[i] = acc[i] * ni + b[c * 8 + i];
    }
    if (RELU) {
#pragma unroll
        for (int i = 0; i < 8; i++) acc[i] = fmaxf(acc[i], 0.f);
    }
    if (ONORM) {
        float no = g_norm_out[node];
#pragma unroll
        for (int i = 0; i < 8; i++) acc[i] *= no;
    }
    if (OH) {
        __half2 h0 = __floats2half2_rn(acc[0], acc[1]);
        __half2 h1 = __floats2half2_rn(acc[2], acc[3]);
        __half2 h2 = __floats2half2_rn(acc[4], acc[5]);
        __half2 h3 = __floats2half2_rn(acc[6], acc[7]);
        uint4 r;
        r.x = *(const unsigned*)&h0; r.y = *(const unsigned*)&h1;
        r.z = *(const unsigned*)&h2; r.w = *(const unsigned*)&h3;
        ((uint4*)outp)[(size_t)node * NT + c] = r;
    } else {
        float* o = (float*)outp + (size_t)node * F + c * 8;
        *(float4*)(o + 0) = make_float4(acc[0], acc[1], acc[2], acc[3]);
        *(float4*)(o + 4) = make_float4(acc[4], acc[5], acc[6], acc[7]);
    }
}

// ---- tensor-core GEMM: D[M,N] = A[M,K] @ W[K,N], fp16 in / fp32 acc --------
// A row-major fp16. Wt[N,K] row-major fp16 (transposed).

template <int K, int N>
__global__ void mma_gemm_k(const __half* __restrict__ A,
                           const __half* __restrict__ Wt,
                           __half* __restrict__ D) {
    constexpr int WN = (N >= 64) ? 64 : N;       // warp n-extent
    constexpr int TN = WN / 8;                   // n8 tiles per warp
    constexpr int WARPS_N = N / WN;
    constexpr int WARPS_M = 8 / WARPS_N;
    constexpr int BM = WARPS_M * 16;
    constexpr int PITCH = K + 8;                 // +16B pad -> bank rotation
    constexpr int KC = K / 16;                   // k16 chunks

    __shared__ __half sA[BM * PITCH];

    const int tid = threadIdx.x;
    const int lane = tid & 31;
    const int wid = tid >> 5;
    const int wm = wid % WARPS_M;
    const int wn = wid / WARPS_M;
    const int blockStart = blockIdx.x * BM;

    for (int i = tid; i < BM * (K / 8); i += 256) {
        int row = i / (K / 8), chunk = i % (K / 8);
        int node = blockStart + row;
        uint4 v = make_uint4(0, 0, 0, 0);
        if (node < NN) v = ((const uint4*)A)[(size_t)node * (K / 8) + chunk];
        *(uint4*)(&sA[row * PITCH + chunk * 8]) = v;
    }
    __syncthreads();

    float acc[TN][4];
#pragma unroll
    for (int t = 0; t < TN; t++)
#pragma unroll
        for (int i = 0; i < 4; i++) acc[t][i] = 0.f;

    const int q = lane >> 3, r = lane & 7;
    const int arow = wm * 16 + r + 8 * (q & 1);
    const int acol0 = 8 * (q >> 1);
    unsigned abase;
    {
        const void* p = &sA[arow * PITCH + acol0];
        asm("{ .reg .u64 t; cvta.to.shared.u64 t, %1; cvt.u32.u64 %0, t; }"
            : "=r"(abase) : "l"(p));
    }

    const __half* wbase = Wt + (size_t)(wn * WN + (lane >> 2)) * K + (lane & 3) * 2;

#pragma unroll
    for (int kc = 0; kc < KC; kc++) {
        unsigned a0, a1, a2, a3;
        asm volatile("ldmatrix.sync.aligned.m8n8.x4.shared.b16 {%0,%1,%2,%3}, [%4];"
                     : "=r"(a0), "=r"(a1), "=r"(a2), "=r"(a3)
                     : "r"(abase + kc * 32));
#pragma unroll
        for (int tn = 0; tn < TN; tn++) {
            unsigned b0 = *(const unsigned*)(wbase + (size_t)tn * 8 * K + kc * 16);
            unsigned b1 = *(const unsigned*)(wbase + (size_t)tn * 8 * K + kc * 16 + 8);
            asm volatile(
                "mma.sync.aligned.m16n8k16.row.col.f32.f16.f16.f32 "
                "{%0,%1,%2,%3}, {%4,%5,%6,%7}, {%8,%9}, {%0,%1,%2,%3};"
                : "+f"(acc[tn][0]), "+f"(acc[tn][1]), "+f"(acc[tn][2]), "+f"(acc[tn][3])
                : "r"(a0), "r"(a1), "r"(a2), "r"(a3), "r"(b0), "r"(b1));
        }
    }

    const int node0 = blockStart + wm * 16 + (lane >> 2);
    const int node1 = node0 + 8;
#pragma unroll
    for (int tn = 0; tn < TN; tn++) {
        int gcol = wn * WN + tn * 8 + (lane & 3) * 2;
        if (node0 < NN) {
            __half2 h = __floats2half2_rn(acc[tn][0], acc[tn][1]);
            *(unsigned*)(D + (size_t)node0 * N + gcol) = *(const unsigned*)&h;
        }
        if (node1 < NN) {
            __half2 h = __floats2half2_rn(acc[tn][2], acc[tn][3]);
            *(unsigned*)(D + (size_t)node1 * N + gcol) = *(const unsigned*)&h;
        }
    }
}

// ---- gemm1: agg16 @ W1 (16x256), fused in_norm+bias+relu, fp16 out ---------

__global__ void gemm1_k(const float* __restrict__ h, const float* __restrict__ W,
                        const float* __restrict__ b, __half* __restrict__ out) {
    __shared__ float sh[64 * 16];
    const int j = threadIdx.x;
    float w[16];
#pragma unroll
    for (int k = 0; k < 16; k++) w[k] = W[k * 256 + j];
    float bj = b[j];
    int nbase = blockIdx.x * 64;
    for (int i = j; i < 64 * 16; i += 256) {
        int node = nbase + i / 16;
        sh[i] = (node < NN) ? h[(size_t)node * 16 + (i % 16)] : 0.f;
    }
    __syncthreads();
#pragma unroll 4
    for (int ln = 0; ln < 64; ln++) {
        int node = nbase + ln;
        if (node >= NN) break;
        float acc = 0.f;
#pragma unroll
        for (int k = 0; k < 16; k++) acc += sh[ln * 16 + k] * w[k];
        acc = acc * g_norm_in[node] + bj;
        out[(size_t)node * 256 + j] = __float2half(fmaxf(acc, 0.f));
    }
}

// ---- gemm5: 32 -> 4 (tiny fp32), thread = node -----------------------------

__global__ void gemm5_k(const float* __restrict__ h, const float* __restrict__ W,
                        float* __restrict__ out) {
    __shared__ float sw[32 * 4];
    if (threadIdx.x < 128) sw[threadIdx.x] = W[threadIdx.x];
    __syncthreads();
    int node = blockIdx.x * 256 + threadIdx.x;
    if (node >= NN) return;
    float no = g_norm_out[node];
    float acc[4] = {0.f, 0.f, 0.f, 0.f};
    const float4* row = (const float4*)(h + (size_t)node * 32);
#pragma unroll
    for (int k4 = 0; k4 < 8; k4++) {
        float4 v = row[k4];
        float vv[4] = {v.x * no, v.y * no, v.z * no, v.w * no};
#pragma unroll
        for (int i = 0; i < 4; i++)
#pragma unroll
            for (int j = 0; j < 4; j++)
                acc[j] += vv[i] * sw[(k4 * 4 + i) * 4 + j];
    }
    *(float4*)(out + (size_t)node * 4) = make_float4(acc[0], acc[1], acc[2], acc[3]);
}

// ---------------------------------------------------------------------------

static inline int cdiv(long long a, int b) { return (int)((a + b - 1) / b); }

extern "C" void kernel_launch(void* const* d_in, const int* in_sizes, int n_in,
                              void* d_out, int out_size) {
    (void)in_sizes; (void)n_in; (void)out_size;
    const float* x    = (const float*)d_in[0];
    const float* efet = (const float*)d_in[1];
    const int*   src  = (const int*)d_in[2];
    const int*   dst  = (const int*)d_in[3];
    const float* W1 = (const float*)d_in[4];  const float* b1 = (const float*)d_in[5];
    const float* W2 = (const float*)d_in[6];  const float* b2 = (const float*)d_in[7];
    const float* W3 = (const float*)d_in[8];  const float* b3 = (const float*)d_in[9];
    const float* W4 = (const float*)d_in[10]; const float* b4 = (const float*)d_in[11];
    const float* W5 = (const float*)d_in[12]; const float* b5 = (const float*)d_in[13];
    float* out = (float*)d_out;

    float *bufA, *bufB, *bufC;
    int *ideg, *odeg, *cnt;
    __half *w2t, *w3t, *w4t;
    cudaGetSymbolAddress((void**)&bufA, g_bufA);
    cudaGetSymbolAddress((void**)&bufB, g_bufB);
    cudaGetSymbolAddress((void**)&bufC, g_bufC);
    cudaGetSymbolAddress((void**)&ideg, g_ideg);
    cudaGetSymbolAddress((void**)&odeg, g_odeg);
    cudaGetSymbolAddress((void**)&cnt,  g_cnt);
    cudaGetSymbolAddress((void**)&w2t, g_w2t);
    cudaGetSymbolAddress((void**)&w3t, g_w3t);
    cudaGetSymbolAddress((void**)&w4t, g_w4t);
    __half* hA = (__half*)bufA;
    __half* hB = (__half*)bufB;
    __half* hC = (__half*)bufC;

    const int TB = 256;

    // ---- preprocessing: degrees, norms, CSR, fp16 transposed weights (R5 form)
    cudaMemsetAsync(ideg, 0, NN * sizeof(int));
    cudaMemsetAsync(odeg, 0, NN * sizeof(int));
    cudaMemsetAsync(cnt,  0, NN * sizeof(int));
    deg_k<<<cdiv(NE, TB), TB>>>(src, dst);
    norm_k<<<cdiv(NN, TB), TB>>>();
    scan_k<<<1, 1024>>>();
    fill_k<<<cdiv(NE, TB), TB>>>(src, dst, efet);
    wcvt_k<256, 128><<<cdiv(256 * 128, TB), TB>>>(W2, w2t);
    wcvt_k<128, 64><<<cdiv(128 * 64, TB), TB>>>(W3, w3t);
    wcvt_k<64, 32><<<cdiv(64 * 32, TB), TB>>>(W4, w4t);

    // ---- gc1: pre-aggregate 16-wide scaled x, matmul+epi+relu -> g1 fp16
    gather_k<16, 2, false, false><<<cdiv(NN, 64), TB>>>(x, nullptr, bufA);
    gemm1_k<<<cdiv(NN, 64), TB>>>(bufA, W1, b1, hB);                          // g1: hB

    // ---- y1 = g1 @ W2 (mma 256->128) BEFORE ewa1 (commuted)
    mma_gemm_k<256, 128><<<cdiv(NN, 64), TB>>>(hB, w2t, hA);                  // y1: hA
    // ---- ewa1 at width 128: m2 = ewa(y1) * out_norm (relu is identity)
    gather_h_k<128, 1, false, false, true, true><<<cdiv(NN, 16), TB>>>(hA, nullptr, hC);
    // ---- gc2 aggregation: g2 = relu(agg(m2)*ni + b2)
    gather_h_k<128, 0, true, true, false, true><<<cdiv(NN, 16), TB>>>(hC, b2, hB); // g2: hB

    // ---- y2 = g2 @ W3 (mma 128->64) BEFORE ewa2
    mma_gemm_k<128, 64><<<cdiv(NN, 128), TB>>>(hB, w3t, hA);                  // y2: hA
    // ---- ewa2 at width 64
    gather_h_k<64, 1, false, false, true, true><<<cdiv(NN, 32), TB>>>(hA, nullptr, hC);
    // ---- gc3 aggregation: g3 = relu(agg(m3)*ni + b3)
    gather_h_k<64, 0, true, true, false, true><<<cdiv(NN, 32), TB>>>(hC, b3, hB);  // g3: hB

    // ---- y3 = g3 @ W4 (mma 64->32) BEFORE ewa3
    mma_gemm_k<64, 32><<<cdiv(NN, 128), TB>>>(hB, w4t, hA);                   // y3: hA
    // ---- ewa3 at width 32
    gather_h_k<32, 1, false, false, true, true><<<cdiv(NN, 64), TB>>>(hA, nullptr, hC);
    // ---- gc4 aggregation: h4 = relu(agg(m4)*ni + b4) -> fp32
    gather_h_k<32, 0, true, true, false, false><<<cdiv(NN, 64), TB>>>(hC, b4, bufB);

    // ---- gc5: m5 = (h4*no) @ W5, then agg*ni + b5
    gemm5_k<<<cdiv(NN, 256), TB>>>(bufB, W5, bufA);                           // m5: bufA
    gather_k<4, 0, true, false><<<cdiv(NN, 256), TB>>>(bufA, b5, out);
}